// round 5
// baseline (speedup 1.0000x reference)
#include <cuda_runtime.h>
#include <cuda_bf16.h>
#include <cstdint>

// Sobel gradient magnitude, zero-padded, on [B=8, C=64, H=256, W=256] fp32.
// out = sqrt(gv^2 + gh^2 + 1e-6), gv = x[i+1,j]-x[i-1,j], gh = x[i,j+1]-x[i,j-1].
//
// Round 5: persistent grid-stride version of the R4 winner (4 rows/thread,
// rolling 3-vector window, shuffle horizontal neighbors, streaming stores).
// Grid = 148 SMs x 8 CTAs exactly -> single wave, no wave-transition overhead.
// Stride = 1184*256 = 303,104 = 74 * 4096 (plane size), so col4 / rq / all
// boundary predicates are loop-invariant; only the plane index advances (+74).
//
// Layout: W4 = 64 float4 per row, H = 256 rows, plane = 2^14 float4, 512 planes.

static constexpr int W4 = 64;

__global__ __launch_bounds__(256, 7)
void sobel_grad_mag_gs(const float4* __restrict__ in,
                       float4* __restrict__ out,
                       int nthreads)
{
    const int t0     = blockIdx.x * blockDim.x + threadIdx.x;
    const int stride = gridDim.x * blockDim.x;          // 303,104 (= 74 planes)
    if (t0 >= nthreads) return;

    // loop-invariant geometry (stride is a multiple of 4096)
    const int lane = threadIdx.x & 31;
    const int col4 = t0 & (W4 - 1);
    const int rq   = (t0 >> 6) & 63;                    // rows 4*rq .. 4*rq+3
    const bool top = (rq == 0);
    const bool bot = (rq == 63);
    const bool need_l = (lane == 0)  && (col4 != 0);
    const bool need_r = (lane == 31) && (col4 != W4 - 1);

    const float4 zero = make_float4(0.f, 0.f, 0.f, 0.f);
    const float* sc = reinterpret_cast<const float*>(in);
    const float EPS = 1e-6f;

    const int istride = (stride >> 12) << 14;           // 74 planes worth of float4
    int i0 = ((t0 >> 12) << 14) | (rq << 8) | col4;

    for (int t = t0; t < nthreads; t += stride, i0 += istride) {
        // rolling window: up / c / dn
        float4 up = top ? zero : __ldg(&in[i0 - W4]);
        float4 c  = __ldg(&in[i0]);
        float4 dn = __ldg(&in[i0 + W4]);

        #pragma unroll
        for (int k = 0; k < 4; k++) {
            float4 nxt;
            if (k < 3) {
                nxt = (k == 2 && bot) ? zero : __ldg(&in[i0 + (k + 2) * W4]);
            }

            float l = __shfl_up_sync(0xffffffffu, c.w, 1);
            float r = __shfl_down_sync(0xffffffffu, c.x, 1);
            if (lane == 0)
                l = need_l ? sc[(size_t)(i0 + k * W4) * 4 - 1] : 0.f;
            if (lane == 31)
                r = need_r ? sc[(size_t)(i0 + k * W4) * 4 + 4] : 0.f;

            const float gv0 = dn.x - up.x;
            const float gv1 = dn.y - up.y;
            const float gv2 = dn.z - up.z;
            const float gv3 = dn.w - up.w;

            const float gh0 = c.y - l;
            const float gh1 = c.z - c.x;
            const float gh2 = c.w - c.y;
            const float gh3 = r   - c.z;

            float4 res;
            res.x = sqrtf(fmaf(gv0, gv0, fmaf(gh0, gh0, EPS)));
            res.y = sqrtf(fmaf(gv1, gv1, fmaf(gh1, gh1, EPS)));
            res.z = sqrtf(fmaf(gv2, gv2, fmaf(gh2, gh2, EPS)));
            res.w = sqrtf(fmaf(gv3, gv3, fmaf(gh3, gh3, EPS)));

            __stcs(&out[i0 + k * W4], res);

            up = c;
            c  = dn;
            if (k < 3) dn = nxt;
        }
    }
}

extern "C" void kernel_launch(void* const* d_in, const int* in_sizes, int n_in,
                              void* d_out, int out_size)
{
    const float4* x = reinterpret_cast<const float4*>(d_in[0]);
    float4* o       = reinterpret_cast<float4*>(d_out);

    // total float4 outputs = out_size/4; each thread-iteration produces 4
    int nthreads = out_size / 16;     // 2,097,152 row-quads
    int threads  = 256;
    int blocks   = 148 * 8;           // 1184 CTAs: single persistent wave

    sobel_grad_mag_gs<<<blocks, threads>>>(x, o, nthreads);
}

// round 6
// speedup vs baseline: 1.1199x; 1.1199x over previous
#include <cuda_runtime.h>
#include <cuda_bf16.h>
#include <cstdint>

// Sobel gradient magnitude, zero-padded, on [B=8, C=64, H=256, W=256] fp32.
// out = sqrt(gv^2 + gh^2 + 1e-6), gv = x[i+1,j]-x[i-1,j], gh = x[i,j+1]-x[i,j-1].
//
// Round 6: 8 rows per thread with the ROLLING 3-vector window from R4.
// Live registers are blocking-depth independent (up/c/dn/nxt only), so this
// gets R3's read redundancy (10 loads / 8 outputs = 1.25 vec loads/output)
// at R4's register budget (32 regs -> 8 CTAs/SM). Non-persistent launch
// (R5 showed the HW work distributor hides wave transitions; a persistent
// loop only serialized memory issue).
//
// Layout: W4 = 64 float4 per row, H = 256 rows, plane = 2^14 float4.
// Thread t: col4 = t & 63, row-octet ro = (t>>6) & 31, plane = t >> 11.
// Warp = 32 consecutive t -> 32 consecutive col4 (never wraps a row).

static constexpr int W4 = 64;

__global__ __launch_bounds__(256, 8)
void sobel_grad_mag_r8w(const float4* __restrict__ in,
                        float4* __restrict__ out,
                        int nthreads)
{
    int t = blockIdx.x * blockDim.x + threadIdx.x;
    if (t >= nthreads) return;

    const int lane = threadIdx.x & 31;
    const int col4 = t & (W4 - 1);
    const int ro   = (t >> 6) & 31;                 // rows 8*ro .. 8*ro+7
    const int i0   = ((t >> 11) << 14) | (ro << 9) | col4;

    const float4 zero = make_float4(0.f, 0.f, 0.f, 0.f);
    const float* sc = reinterpret_cast<const float*>(in);
    const float EPS = 1e-6f;
    const bool need_l = (lane == 0)  && (col4 != 0);
    const bool need_r = (lane == 31) && (col4 != W4 - 1);

    // rolling window: up / c / dn, with dn of iteration k+1 loaded during k
    float4 up = (ro == 0) ? zero : __ldg(&in[i0 - W4]);
    float4 c  = __ldg(&in[i0]);
    float4 dn = __ldg(&in[i0 + W4]);

    #pragma unroll
    for (int k = 0; k < 8; k++) {
        // issue next row's load before this iteration's compute
        float4 nxt;
        if (k < 7) {
            nxt = (k == 6 && ro == 31) ? zero : __ldg(&in[i0 + (k + 2) * W4]);
        }

        // horizontal neighbors from adjacent lanes (same row vector)
        float l = __shfl_up_sync(0xffffffffu, c.w, 1);
        float r = __shfl_down_sync(0xffffffffu, c.x, 1);
        if (lane == 0)
            l = need_l ? sc[(size_t)(i0 + k * W4) * 4 - 1] : 0.f;
        if (lane == 31)
            r = need_r ? sc[(size_t)(i0 + k * W4) * 4 + 4] : 0.f;

        const float gv0 = dn.x - up.x;
        const float gv1 = dn.y - up.y;
        const float gv2 = dn.z - up.z;
        const float gv3 = dn.w - up.w;

        const float gh0 = c.y - l;
        const float gh1 = c.z - c.x;
        const float gh2 = c.w - c.y;
        const float gh3 = r   - c.z;

        float4 res;
        res.x = sqrtf(fmaf(gv0, gv0, fmaf(gh0, gh0, EPS)));
        res.y = sqrtf(fmaf(gv1, gv1, fmaf(gh1, gh1, EPS)));
        res.z = sqrtf(fmaf(gv2, gv2, fmaf(gh2, gh2, EPS)));
        res.w = sqrtf(fmaf(gv3, gv3, fmaf(gh3, gh3, EPS)));

        __stcs(&out[i0 + k * W4], res);

        // rotate window
        up = c;
        c  = dn;
        if (k < 7) dn = nxt;
    }
}

extern "C" void kernel_launch(void* const* d_in, const int* in_sizes, int n_in,
                              void* d_out, int out_size)
{
    const float4* x = reinterpret_cast<const float4*>(d_in[0]);
    float4* o       = reinterpret_cast<float4*>(d_out);

    // total float4 outputs = out_size/4; each thread produces 8 of them
    int nthreads = out_size / 32;   // 1,048,576
    int threads  = 256;
    int blocks   = (nthreads + threads - 1) / threads;

    sobel_grad_mag_r8w<<<blocks, threads>>>(x, o, nthreads);
}

// round 7
// speedup vs baseline: 1.1882x; 1.0610x over previous
#include <cuda_runtime.h>
#include <cuda_bf16.h>
#include <cstdint>

// Sobel gradient magnitude, zero-padded, on [B=8, C=64, H=256, W=256] fp32.
// out = sqrt(gv^2 + gh^2 + 1e-6), gv = x[i+1,j]-x[i-1,j], gh = x[i,j+1]-x[i,j-1].
//
// Round 7: micro-tune of the R4 winner (4 rows/thread, rolling 3-vector window,
// shuffle horizontal neighbors, streaming stores):
//   - 512-thread blocks, __launch_bounds__(512, 4): same 64 warps/SM budget,
//     half the CTA count -> fewer per-CTA launch/drain events.
//   - exact grid, no bounds guard (2,097,152 threads = 4096 x 512 exactly).
//   - first 'nxt' row issued with the prologue loads (MLP_p1 = 4).
//
// Layout: W4 = 64 float4 per row, H = 256 rows, plane = 2^14 float4.
// Thread t: col4 = t & 63, row-quad rq = (t>>6) & 63, plane = t >> 12.
// Warp = 32 consecutive t -> 32 consecutive col4 (never wraps a row).

static constexpr int W4 = 64;

__global__ __launch_bounds__(512, 4)
void sobel_grad_mag_r7(const float4* __restrict__ in,
                       float4* __restrict__ out)
{
    const int t = blockIdx.x * blockDim.x + threadIdx.x;

    const int lane = threadIdx.x & 31;
    const int col4 = t & (W4 - 1);
    const int rq   = (t >> 6) & 63;                 // rows 4*rq .. 4*rq+3
    const int i0   = ((t >> 12) << 14) | (rq << 8) | col4;

    const float4 zero = make_float4(0.f, 0.f, 0.f, 0.f);
    const float* sc = reinterpret_cast<const float*>(in);
    const float EPS = 1e-6f;
    const bool need_l = (lane == 0)  && (col4 != 0);
    const bool need_r = (lane == 31) && (col4 != W4 - 1);

    // prologue: 4 front-issued loads (up, c, dn, first nxt)
    float4 up  = (rq == 0) ? zero : __ldg(&in[i0 - W4]);
    float4 c   = __ldg(&in[i0]);
    float4 dn  = __ldg(&in[i0 + W4]);
    float4 nx0 = __ldg(&in[i0 + 2 * W4]);

    #pragma unroll
    for (int k = 0; k < 4; k++) {
        // next row's load for iteration k+1 (k=0 already has nx0)
        float4 nxt;
        if (k == 0) {
            nxt = nx0;
        } else if (k < 3) {
            nxt = (k == 2 && rq == 63) ? zero : __ldg(&in[i0 + (k + 2) * W4]);
        }

        // horizontal neighbors from adjacent lanes (same row vector)
        float l = __shfl_up_sync(0xffffffffu, c.w, 1);
        float r = __shfl_down_sync(0xffffffffu, c.x, 1);
        if (lane == 0)
            l = need_l ? sc[(size_t)(i0 + k * W4) * 4 - 1] : 0.f;
        if (lane == 31)
            r = need_r ? sc[(size_t)(i0 + k * W4) * 4 + 4] : 0.f;

        const float gv0 = dn.x - up.x;
        const float gv1 = dn.y - up.y;
        const float gv2 = dn.z - up.z;
        const float gv3 = dn.w - up.w;

        const float gh0 = c.y - l;
        const float gh1 = c.z - c.x;
        const float gh2 = c.w - c.y;
        const float gh3 = r   - c.z;

        float4 res;
        res.x = sqrtf(fmaf(gv0, gv0, fmaf(gh0, gh0, EPS)));
        res.y = sqrtf(fmaf(gv1, gv1, fmaf(gh1, gh1, EPS)));
        res.z = sqrtf(fmaf(gv2, gv2, fmaf(gh2, gh2, EPS)));
        res.w = sqrtf(fmaf(gv3, gv3, fmaf(gh3, gh3, EPS)));

        __stcs(&out[i0 + k * W4], res);

        // rotate window
        up = c;
        c  = dn;
        if (k < 3) dn = nxt;
    }
}

extern "C" void kernel_launch(void* const* d_in, const int* in_sizes, int n_in,
                              void* d_out, int out_size)
{
    const float4* x = reinterpret_cast<const float4*>(d_in[0]);
    float4* o       = reinterpret_cast<float4*>(d_out);

    // total float4 outputs = out_size/4; each thread produces 4 of them
    int nthreads = out_size / 16;   // 2,097,152 (exactly 4096 * 512)
    int threads  = 512;
    int blocks   = nthreads / threads;

    sobel_grad_mag_r7<<<blocks, threads>>>(x, o);
}